// round 9
// baseline (speedup 1.0000x reference)
#include <cuda_runtime.h>
#include <cuda_bf16.h>
#include <math.h>

#define MAXN 50000
#define MAXE 800000

typedef unsigned long long u64;

// ---------------- scratch (static device globals; no allocs allowed) ----------------
__device__ int   g_cnt[MAXN];            // zeroed at static init; scan re-zeroes after read
__device__ int   g_off[MAXN + 1];
__device__ int   g_cursor[MAXN];
__device__ volatile u64 g_state[64];     // lookback states; zeroed by k_count block 0
__device__ float g_dis[MAXN];
__device__ int2  g_csr[MAXE];            // {src row, float bits of dis[src]}
__device__ float g_xw1[(size_t)MAXN * 64];  // x@W1 (raw)
__device__ float g_h  [(size_t)MAXN * 64];  // relu(layer1)
__device__ float g_xw2[(size_t)MAXN * 64];  // h@W2 (raw)
__device__ float g_z  [(size_t)MAXN * 64];  // layer2 out

// ---------------- streams/events (host-side, created once) ----------------
static cudaStream_t g_s2;
static cudaEvent_t  g_evF, g_evJ;
struct _AthInit {
    _AthInit() {
        cudaStreamCreateWithFlags(&g_s2, cudaStreamNonBlocking);
        cudaEventCreateWithFlags(&g_evF, cudaEventDisableTiming);
        cudaEventCreateWithFlags(&g_evJ, cudaEventDisableTiming);
    }
};
static _AthInit _ath_init;

// ---------------- CSR build ----------------
__global__ void k_count(const int* __restrict__ ei, int nE) {
    if (blockIdx.x == 0 && threadIdx.x < 64) g_state[threadIdx.x] = 0;
    int e = blockIdx.x * blockDim.x + threadIdx.x;
    if (e < nE) atomicAdd(&g_cnt[ei[nE + e]], 1);  // col = target
}

// fused scan: exclusive offsets + cursor init + dis, single kernel.
__global__ void k_scan_fused(int n, int nb) {
    __shared__ int s[1024];
    __shared__ int s_excl;
    __shared__ int r64[2];
    int b = blockIdx.x, t = threadIdx.x;
    int i = b * 1024 + t;
    int v = (i < n) ? g_cnt[i] : 0;
    if (i < n) g_cnt[i] = 0;              // restore invariant for next replay
    s[t] = v;
    __syncthreads();
#pragma unroll
    for (int dd = 1; dd < 1024; dd <<= 1) {
        int x = (t >= dd) ? s[t - dd] : 0;
        __syncthreads();
        s[t] += x;
        __syncthreads();
    }
    int incl = s[t];
    if (t == 1023)
        g_state[b] = (1ull << 32) | (unsigned)incl;   // publish block aggregate
    if (t < 64) {
        int val = 0;
        if (t < b) {
            u64 st;
            do { st = g_state[t]; } while (!(st >> 32));
            val = (int)(unsigned)st;
        }
#pragma unroll
        for (int o = 16; o; o >>= 1) val += __shfl_down_sync(0xffffffffu, val, o);
        if ((t & 31) == 0) r64[t >> 5] = val;
    }
    __syncthreads();
    if (t == 0) s_excl = r64[0] + r64[1];
    __syncthreads();
    int ex = s_excl;
    if (i < n) {
        int o = ex + incl - v;
        g_off[i] = o;
        g_cursor[i] = o;
        g_dis[i] = rsqrtf((float)(v + 1));   // deg = in-degree + self-loop
    }
    if (b == nb - 1 && t == 1023) g_off[n] = ex + incl;
}

__global__ void k_scatter(const int* __restrict__ ei, int nE) {
    int e = blockIdx.x * blockDim.x + threadIdx.x;
    if (e < nE) {
        int row = ei[e];
        int col = ei[nE + e];
        int p = atomicAdd(&g_cursor[col], 1);
        g_csr[p] = make_int2(row, __float_as_int(g_dis[row]));
    }
}

// ---------------- tensor-core GEMM with bf16 2-term split ----------------
// D = xh@Wh + xh@Wl + xl@Wh  (fp32 accum; dropped xl@Wl ~ 2^-18 rel)
__device__ __forceinline__ void split_pack(float a, float b, unsigned& hi, unsigned& lo) {
    __nv_bfloat16 ha = __float2bfloat16_rn(a), hb = __float2bfloat16_rn(b);
    float ra = a - __bfloat162float(ha);
    float rb = b - __bfloat162float(hb);
    __nv_bfloat16 la = __float2bfloat16_rn(ra), lb = __float2bfloat16_rn(rb);
    hi = ((unsigned)__bfloat16_as_ushort(hb) << 16) | (unsigned)__bfloat16_as_ushort(ha);
    lo = ((unsigned)__bfloat16_as_ushort(lb) << 16) | (unsigned)__bfloat16_as_ushort(la);
}

__device__ __forceinline__ void ldsm4(unsigned* r, unsigned addr) {
    asm volatile("ldmatrix.sync.aligned.m8n8.x4.shared.b16 {%0,%1,%2,%3}, [%4];"
        : "=r"(r[0]), "=r"(r[1]), "=r"(r[2]), "=r"(r[3]) : "r"(addr));
}
__device__ __forceinline__ void ldsm4t(unsigned* r, unsigned addr) {
    asm volatile("ldmatrix.sync.aligned.m8n8.x4.trans.shared.b16 {%0,%1,%2,%3}, [%4];"
        : "=r"(r[0]), "=r"(r[1]), "=r"(r[2]), "=r"(r[3]) : "r"(addr));
}
__device__ __forceinline__ void mma16816(float* c, const unsigned* a, const unsigned* b) {
    asm volatile(
        "mma.sync.aligned.m16n8k16.row.col.f32.bf16.bf16.f32 "
        "{%0,%1,%2,%3}, {%4,%5,%6,%7}, {%8,%9}, {%0,%1,%2,%3};"
        : "+f"(c[0]), "+f"(c[1]), "+f"(c[2]), "+f"(c[3])
        : "r"(a[0]), "r"(a[1]), "r"(a[2]), "r"(a[3]), "r"(b[0]), "r"(b[1]));
}

// Block tile 128(M) x 64(N), 256 threads = 8 warps (4M x 2N), warp tile 32x32.
// Software-pipelined: next chunk's global loads issued before this chunk's mma.
template <int K>
__global__ void __launch_bounds__(256) k_gemm_mma(const float* __restrict__ A,
                                                  const float* __restrict__ W,
                                                  float* __restrict__ out, int n) {
    constexpr int PA = 40;   // bf16 pitch for x tiles
    constexpr int PB = 72;   // bf16 pitch for w tiles
    constexpr int NC = K / 32;
    __shared__ __align__(16) __nv_bfloat16 xh[128 * PA], xl[128 * PA];
    __shared__ __align__(16) __nv_bfloat16 wh[32 * PB],  wl[32 * PB];
    int t = threadIdx.x;
    int lane = t & 31, wrp = t >> 5;
    int wm = wrp & 3, wn = wrp >> 2;
    int row0 = blockIdx.x * 128;

    float acc[2][4][4] = {};

    unsigned sxh = (unsigned)__cvta_generic_to_shared(xh);
    unsigned sxl = (unsigned)__cvta_generic_to_shared(xl);
    unsigned swh = (unsigned)__cvta_generic_to_shared(wh);
    unsigned swl = (unsigned)__cvta_generic_to_shared(wl);

    float4 px[4], pw[2];
    // staging indices (fixed per thread)
    int xr[4], xc[4], wr[2], wc[2];
#pragma unroll
    for (int it = 0; it < 4; it++) {
        int v = it * 256 + t;
        xr[it] = v >> 3; xc[it] = v & 7;
    }
#pragma unroll
    for (int it = 0; it < 2; it++) {
        int v = it * 256 + t;
        wr[it] = v >> 4; wc[it] = v & 15;
    }

    // prologue: load chunk 0
#pragma unroll
    for (int it = 0; it < 4; it++) {
        int gr = min(row0 + xr[it], n - 1);
        px[it] = *(const float4*)(A + (size_t)gr * K + xc[it] * 4);
    }
#pragma unroll
    for (int it = 0; it < 2; it++)
        pw[it] = *(const float4*)(W + (size_t)wr[it] * 64 + wc[it] * 4);

#pragma unroll
    for (int c = 0; c < NC; c++) {
        // convert & store current chunk to smem
#pragma unroll
        for (int it = 0; it < 4; it++) {
            uint2 h, l;
            split_pack(px[it].x, px[it].y, h.x, l.x);
            split_pack(px[it].z, px[it].w, h.y, l.y);
            *(uint2*)&xh[xr[it] * PA + xc[it] * 4] = h;
            *(uint2*)&xl[xr[it] * PA + xc[it] * 4] = l;
        }
#pragma unroll
        for (int it = 0; it < 2; it++) {
            uint2 h, l;
            split_pack(pw[it].x, pw[it].y, h.x, l.x);
            split_pack(pw[it].z, pw[it].w, h.y, l.y);
            *(uint2*)&wh[wr[it] * PB + wc[it] * 4] = h;
            *(uint2*)&wl[wr[it] * PB + wc[it] * 4] = l;
        }
        __syncthreads();

        // prefetch next chunk (LDG overlaps the mma section below)
        if (c + 1 < NC) {
            int kc = (c + 1) * 32;
#pragma unroll
            for (int it = 0; it < 4; it++) {
                int gr = min(row0 + xr[it], n - 1);
                px[it] = *(const float4*)(A + (size_t)gr * K + kc + xc[it] * 4);
            }
#pragma unroll
            for (int it = 0; it < 2; it++)
                pw[it] = *(const float4*)(W + (size_t)(kc + wr[it]) * 64 + wc[it] * 4);
        }

#pragma unroll
        for (int ks = 0; ks < 32; ks += 16) {
            unsigned ah[2][4], al[2][4], bh[2][4], bl[2][4];
#pragma unroll
            for (int mi = 0; mi < 2; mi++) {
                int rrow = wm * 32 + mi * 16 + (lane & 15);
                unsigned off = (unsigned)(rrow * PA + ks) * 2 + (lane >> 4) * 16;
                ldsm4(ah[mi], sxh + off);
                ldsm4(al[mi], sxl + off);
            }
#pragma unroll
            for (int nb = 0; nb < 2; nb++) {
                int kk = ks + (lane & 7) + ((lane >> 3) & 1) * 8;
                int nc = wn * 32 + nb * 16 + (lane >> 4) * 8;
                unsigned off = (unsigned)(kk * PB + nc) * 2;
                ldsm4t(bh[nb], swh + off);
                ldsm4t(bl[nb], swl + off);
            }
#pragma unroll
            for (int mi = 0; mi < 2; mi++)
#pragma unroll
                for (int nb = 0; nb < 2; nb++)
#pragma unroll
                    for (int q = 0; q < 2; q++) {
                        float* cc = acc[mi][nb * 2 + q];
                        mma16816(cc, ah[mi], &bh[nb][q * 2]);
                        mma16816(cc, ah[mi], &bl[nb][q * 2]);
                        mma16816(cc, al[mi], &bh[nb][q * 2]);
                    }
        }
        __syncthreads();
    }

#pragma unroll
    for (int mi = 0; mi < 2; mi++) {
#pragma unroll
        for (int nj = 0; nj < 4; nj++) {
            int col = wn * 32 + nj * 8 + (lane & 3) * 2;
            int r0 = row0 + wm * 32 + mi * 16 + (lane >> 2);
            if (r0 < n)
                *(float2*)(out + (size_t)r0 * 64 + col) =
                    make_float2(acc[mi][nj][0], acc[mi][nj][1]);
            int r1 = r0 + 8;
            if (r1 < n)
                *(float2*)(out + (size_t)r1 * 64 + col) =
                    make_float2(acc[mi][nj][2], acc[mi][nj][3]);
        }
    }
}

// ---------------- Aggregation (warp per node, 4-way unrolled gathers) ----------------
// out[i] = act( dis[i]*( sum_in xw[row]*dis[row] + xw[i]*dis[i] ) + b )
__global__ void k_aggregate(const float* __restrict__ in, float* __restrict__ out,
                            const float* __restrict__ bias, int n, int relu) {
    int node = blockIdx.x * 8 + (threadIdx.x >> 5);
    int lane = threadIdx.x & 31;
    if (node >= n) return;
    const float2* inp = (const float2*)in;
    float d = g_dis[node];
    float2 self = inp[(size_t)node * 32 + lane];
    float2 acc0 = make_float2(self.x * d, self.y * d);   // self-loop
    float2 acc1 = make_float2(0.f, 0.f);
    int s = g_off[node], e = g_off[node + 1];
    for (int base = s; base < e; base += 32) {
        int idx = base + lane;
        int2 pr = (idx < e) ? g_csr[idx] : make_int2(0, 0);
        int cnt = min(32, e - base);
        int j = 0;
        for (; j + 4 <= cnt; j += 4) {
            int   r0 = __shfl_sync(0xffffffffu, pr.x, j);
            float d0 = __int_as_float(__shfl_sync(0xffffffffu, pr.y, j));
            int   r1 = __shfl_sync(0xffffffffu, pr.x, j + 1);
            float d1 = __int_as_float(__shfl_sync(0xffffffffu, pr.y, j + 1));
            int   r2 = __shfl_sync(0xffffffffu, pr.x, j + 2);
            float d2 = __int_as_float(__shfl_sync(0xffffffffu, pr.y, j + 2));
            int   r3 = __shfl_sync(0xffffffffu, pr.x, j + 3);
            float d3 = __int_as_float(__shfl_sync(0xffffffffu, pr.y, j + 3));
            float2 v0 = inp[(size_t)r0 * 32 + lane];
            float2 v1 = inp[(size_t)r1 * 32 + lane];
            float2 v2 = inp[(size_t)r2 * 32 + lane];
            float2 v3 = inp[(size_t)r3 * 32 + lane];
            acc0.x = fmaf(v0.x, d0, acc0.x); acc0.y = fmaf(v0.y, d0, acc0.y);
            acc1.x = fmaf(v1.x, d1, acc1.x); acc1.y = fmaf(v1.y, d1, acc1.y);
            acc0.x = fmaf(v2.x, d2, acc0.x); acc0.y = fmaf(v2.y, d2, acc0.y);
            acc1.x = fmaf(v3.x, d3, acc1.x); acc1.y = fmaf(v3.y, d3, acc1.y);
        }
        for (; j < cnt; j++) {
            int   r  = __shfl_sync(0xffffffffu, pr.x, j);
            float dw = __int_as_float(__shfl_sync(0xffffffffu, pr.y, j));
            float2 v = inp[(size_t)r * 32 + lane];
            acc0.x = fmaf(v.x, dw, acc0.x);
            acc0.y = fmaf(v.y, dw, acc0.y);
        }
    }
    float ax = acc0.x + acc1.x, ay = acc0.y + acc1.y;
    float2 bv = ((const float2*)bias)[lane];
    float ox = fmaf(d, ax, bv.x);
    float oy = fmaf(d, ay, bv.y);
    if (relu) { ox = fmaxf(ox, 0.f); oy = fmaxf(oy, 0.f); }
    float2 o; o.x = ox; o.y = oy;
    ((float2*)out)[(size_t)node * 32 + lane] = o;
}

// ---------------- Decode: out[e] = dot(z[src], z[dst]) ----------------
__global__ void k_decode(const int* __restrict__ eli, const float* __restrict__ z,
                         float* __restrict__ out, int nL) {
    int w = blockIdx.x * 8 + (threadIdx.x >> 5);
    int lane = threadIdx.x & 31;
    if (w >= nL) return;
    int s = eli[w];
    int d = eli[nL + w];
    const float2* z2 = (const float2*)z;
    float2 a = z2[(size_t)s * 32 + lane];
    float2 b = z2[(size_t)d * 32 + lane];
    float p = a.x * b.x + a.y * b.y;
#pragma unroll
    for (int o = 16; o > 0; o >>= 1) p += __shfl_down_sync(0xffffffffu, p, o);
    if (lane == 0) out[w] = p;
}

// ---------------- launch ----------------
extern "C" void kernel_launch(void* const* d_in, const int* in_sizes, int n_in,
                              void* d_out, int out_size) {
    const float* x   = (const float*)d_in[0];
    const int*   ei  = (const int*)  d_in[1];
    const int*   eli = (const int*)  d_in[2];
    const float* W1  = (const float*)d_in[3];
    const float* b1  = (const float*)d_in[4];
    const float* W2  = (const float*)d_in[5];
    const float* b2  = (const float*)d_in[6];
    float* out = (float*)d_out;

    int n  = in_sizes[0] / 256;
    int nE = in_sizes[1] / 2;
    int nL = in_sizes[2] / 2;

    void *p_xw1, *p_h, *p_xw2, *p_z;
    cudaGetSymbolAddress(&p_xw1, g_xw1);
    cudaGetSymbolAddress(&p_h,   g_h);
    cudaGetSymbolAddress(&p_xw2, g_xw2);
    cudaGetSymbolAddress(&p_z,   g_z);

    // Fork: CSR build on side stream, GEMM1 concurrently on main stream.
    cudaEventRecord(g_evF, 0);
    cudaStreamWaitEvent(g_s2, g_evF, 0);

    k_count<<<(nE + 255) / 256, 256, 0, g_s2>>>(ei, nE);
    int nb = (n + 1023) / 1024;
    k_scan_fused<<<nb, 1024, 0, g_s2>>>(n, nb);
    k_scatter<<<(nE + 255) / 256, 256, 0, g_s2>>>(ei, nE);
    cudaEventRecord(g_evJ, g_s2);

    int gb = (n + 127) / 128;
    k_gemm_mma<256><<<gb, 256>>>(x, W1, (float*)p_xw1, n);   // concurrent with CSR

    // Join
    cudaStreamWaitEvent(0, g_evJ, 0);

    // layer 1 aggregate
    k_aggregate<<<(n + 7) / 8, 256>>>((const float*)p_xw1, (float*)p_h, b1, n, 1);
    // layer 2
    k_gemm_mma<64><<<gb, 256>>>((const float*)p_h, W2, (float*)p_xw2, n);
    k_aggregate<<<(n + 7) / 8, 256>>>((const float*)p_xw2, (float*)p_z, b2, n, 0);
    // decode
    k_decode<<<(nL + 7) / 8, 256>>>(eli, (const float*)p_z, out, nL);
}

// round 10
// speedup vs baseline: 1.0671x; 1.0671x over previous
#include <cuda_runtime.h>
#include <cuda_bf16.h>
#include <math.h>

#define MAXN 50000
#define MAXE 800000

typedef unsigned long long u64;

// ---------------- scratch (static device globals; no allocs allowed) ----------------
__device__ int   g_cnt[MAXN];            // zeroed at static init; scan re-zeroes after read
__device__ int   g_off[MAXN + 1];
__device__ int   g_cursor[MAXN];
__device__ volatile u64 g_state[64];     // lookback states; zeroed by k_count block 0
__device__ float g_dis[MAXN];
__device__ int2  g_csr[MAXE];            // {src row, float bits of dis[src]}
__device__ float g_xw1[(size_t)MAXN * 64];  // x@W1 (raw)
__device__ float g_h  [(size_t)MAXN * 64];  // relu(layer1)
__device__ float g_xw2[(size_t)MAXN * 64];  // h@W2 (raw)
__device__ float g_z  [(size_t)MAXN * 64];  // layer2 out

// ---------------- streams/events (host-side, created once) ----------------
static cudaStream_t g_s2;
static cudaEvent_t  g_evF, g_evJ;
struct _AthInit {
    _AthInit() {
        cudaStreamCreateWithFlags(&g_s2, cudaStreamNonBlocking);
        cudaEventCreateWithFlags(&g_evF, cudaEventDisableTiming);
        cudaEventCreateWithFlags(&g_evJ, cudaEventDisableTiming);
    }
};
static _AthInit _ath_init;

// ---------------- CSR build ----------------
__global__ void k_count(const int* __restrict__ ei, int nE) {
    if (blockIdx.x == 0 && threadIdx.x < 64) g_state[threadIdx.x] = 0;
    int e = blockIdx.x * blockDim.x + threadIdx.x;
    if (e < nE) atomicAdd(&g_cnt[ei[nE + e]], 1);  // col = target
}

// fused scan: exclusive offsets + cursor init + dis, single kernel.
__global__ void k_scan_fused(int n, int nb) {
    __shared__ int s[1024];
    __shared__ int s_excl;
    __shared__ int r64[2];
    int b = blockIdx.x, t = threadIdx.x;
    int i = b * 1024 + t;
    int v = (i < n) ? g_cnt[i] : 0;
    if (i < n) g_cnt[i] = 0;              // restore invariant for next replay
    s[t] = v;
    __syncthreads();
#pragma unroll
    for (int dd = 1; dd < 1024; dd <<= 1) {
        int x = (t >= dd) ? s[t - dd] : 0;
        __syncthreads();
        s[t] += x;
        __syncthreads();
    }
    int incl = s[t];
    if (t == 1023)
        g_state[b] = (1ull << 32) | (unsigned)incl;   // publish block aggregate
    if (t < 64) {
        int val = 0;
        if (t < b) {
            u64 st;
            do { st = g_state[t]; } while (!(st >> 32));
            val = (int)(unsigned)st;
        }
#pragma unroll
        for (int o = 16; o; o >>= 1) val += __shfl_down_sync(0xffffffffu, val, o);
        if ((t & 31) == 0) r64[t >> 5] = val;
    }
    __syncthreads();
    if (t == 0) s_excl = r64[0] + r64[1];
    __syncthreads();
    int ex = s_excl;
    if (i < n) {
        int o = ex + incl - v;
        g_off[i] = o;
        g_cursor[i] = o;
        g_dis[i] = rsqrtf((float)(v + 1));   // deg = in-degree + self-loop
    }
    if (b == nb - 1 && t == 1023) g_off[n] = ex + incl;
}

__global__ void k_scatter(const int* __restrict__ ei, int nE) {
    int e = blockIdx.x * blockDim.x + threadIdx.x;
    if (e < nE) {
        int row = ei[e];
        int col = ei[nE + e];
        int p = atomicAdd(&g_cursor[col], 1);
        g_csr[p] = make_int2(row, __float_as_int(g_dis[row]));
    }
}

// ---------------- tensor-core GEMM with bf16 2-term split ----------------
// D = xh@Wh + xh@Wl + xl@Wh  (fp32 accum; dropped xl@Wl ~ 2^-18 rel)
__device__ __forceinline__ void split_pack(float a, float b, unsigned& hi, unsigned& lo) {
    __nv_bfloat16 ha = __float2bfloat16_rn(a), hb = __float2bfloat16_rn(b);
    float ra = a - __bfloat162float(ha);
    float rb = b - __bfloat162float(hb);
    __nv_bfloat16 la = __float2bfloat16_rn(ra), lb = __float2bfloat16_rn(rb);
    hi = ((unsigned)__bfloat16_as_ushort(hb) << 16) | (unsigned)__bfloat16_as_ushort(ha);
    lo = ((unsigned)__bfloat16_as_ushort(lb) << 16) | (unsigned)__bfloat16_as_ushort(la);
}

__device__ __forceinline__ void ldsm4(unsigned* r, unsigned addr) {
    asm volatile("ldmatrix.sync.aligned.m8n8.x4.shared.b16 {%0,%1,%2,%3}, [%4];"
        : "=r"(r[0]), "=r"(r[1]), "=r"(r[2]), "=r"(r[3]) : "r"(addr));
}
__device__ __forceinline__ void ldsm4t(unsigned* r, unsigned addr) {
    asm volatile("ldmatrix.sync.aligned.m8n8.x4.trans.shared.b16 {%0,%1,%2,%3}, [%4];"
        : "=r"(r[0]), "=r"(r[1]), "=r"(r[2]), "=r"(r[3]) : "r"(addr));
}
__device__ __forceinline__ void mma16816(float* c, const unsigned* a, const unsigned* b) {
    asm volatile(
        "mma.sync.aligned.m16n8k16.row.col.f32.bf16.bf16.f32 "
        "{%0,%1,%2,%3}, {%4,%5,%6,%7}, {%8,%9}, {%0,%1,%2,%3};"
        : "+f"(c[0]), "+f"(c[1]), "+f"(c[2]), "+f"(c[3])
        : "r"(a[0]), "r"(a[1]), "r"(a[2]), "r"(a[3]), "r"(b[0]), "r"(b[1]));
}

// Block tile 128(M) x 64(N), 256 threads = 8 warps (4M x 2N), warp tile 32x32.
// (R8 shape: no register prefetch -> 80 regs, 3 blocks/SM.)
template <int K>
__global__ void __launch_bounds__(256) k_gemm_mma(const float* __restrict__ A,
                                                  const float* __restrict__ W,
                                                  float* __restrict__ out, int n) {
    constexpr int PA = 40;   // bf16 pitch for x tiles (80B: conflict-free ldmatrix)
    constexpr int PB = 72;   // bf16 pitch for w tiles (144B: conflict-free ldmatrix)
    __shared__ __align__(16) __nv_bfloat16 xh[128 * PA], xl[128 * PA];
    __shared__ __align__(16) __nv_bfloat16 wh[32 * PB],  wl[32 * PB];
    int t = threadIdx.x;
    int lane = t & 31, wrp = t >> 5;
    int wm = wrp & 3, wn = wrp >> 2;
    int row0 = blockIdx.x * 128;

    float acc[2][4][4] = {};

    unsigned sxh = (unsigned)__cvta_generic_to_shared(xh);
    unsigned sxl = (unsigned)__cvta_generic_to_shared(xl);
    unsigned swh = (unsigned)__cvta_generic_to_shared(wh);
    unsigned swl = (unsigned)__cvta_generic_to_shared(wl);

    for (int kc = 0; kc < K; kc += 32) {
        // stage x tile: 128 rows x 32 k, convert fp32 -> (hi, lo) bf16
#pragma unroll
        for (int it = 0; it < 4; it++) {
            int v = it * 256 + t;          // 1024 chunks of 4 floats
            int r = v >> 3, ch = v & 7;
            int gr = min(row0 + r, n - 1);
            float4 xv = *(const float4*)(A + (size_t)gr * K + kc + ch * 4);
            uint2 h, l;
            split_pack(xv.x, xv.y, h.x, l.x);
            split_pack(xv.z, xv.w, h.y, l.y);
            *(uint2*)&xh[r * PA + ch * 4] = h;
            *(uint2*)&xl[r * PA + ch * 4] = l;
        }
        // stage w tile: 32 k x 64 cols
#pragma unroll
        for (int it = 0; it < 2; it++) {
            int v = it * 256 + t;          // 512 chunks of 4 floats
            int r = v >> 4, c = v & 15;
            float4 wv = *(const float4*)(W + (size_t)(kc + r) * 64 + c * 4);
            uint2 h, l;
            split_pack(wv.x, wv.y, h.x, l.x);
            split_pack(wv.z, wv.w, h.y, l.y);
            *(uint2*)&wh[r * PB + c * 4] = h;
            *(uint2*)&wl[r * PB + c * 4] = l;
        }
        __syncthreads();

#pragma unroll
        for (int ks = 0; ks < 32; ks += 16) {
            unsigned ah[2][4], al[2][4], bh[2][4], bl[2][4];
#pragma unroll
            for (int mi = 0; mi < 2; mi++) {
                int rrow = wm * 32 + mi * 16 + (lane & 15);
                unsigned off = (unsigned)(rrow * PA + ks) * 2 + (lane >> 4) * 16;
                ldsm4(ah[mi], sxh + off);
                ldsm4(al[mi], sxl + off);
            }
#pragma unroll
            for (int nb = 0; nb < 2; nb++) {
                int kk = ks + (lane & 7) + ((lane >> 3) & 1) * 8;
                int nc = wn * 32 + nb * 16 + (lane >> 4) * 8;
                unsigned off = (unsigned)(kk * PB + nc) * 2;
                ldsm4t(bh[nb], swh + off);
                ldsm4t(bl[nb], swl + off);
            }
#pragma unroll
            for (int mi = 0; mi < 2; mi++)
#pragma unroll
                for (int nb = 0; nb < 2; nb++)
#pragma unroll
                    for (int q = 0; q < 2; q++) {
                        float* c = acc[mi][nb * 2 + q];
                        mma16816(c, ah[mi], &bh[nb][q * 2]);
                        mma16816(c, ah[mi], &bl[nb][q * 2]);
                        mma16816(c, al[mi], &bh[nb][q * 2]);
                    }
        }
        __syncthreads();
    }

#pragma unroll
    for (int mi = 0; mi < 2; mi++) {
#pragma unroll
        for (int nj = 0; nj < 4; nj++) {
            int col = wn * 32 + nj * 8 + (lane & 3) * 2;
            int r0 = row0 + wm * 32 + mi * 16 + (lane >> 2);
            if (r0 < n)
                *(float2*)(out + (size_t)r0 * 64 + col) =
                    make_float2(acc[mi][nj][0], acc[mi][nj][1]);
            int r1 = r0 + 8;
            if (r1 < n)
                *(float2*)(out + (size_t)r1 * 64 + col) =
                    make_float2(acc[mi][nj][2], acc[mi][nj][3]);
        }
    }
}

// ---------------- Aggregation (warp per node, 4-way unrolled gathers) ----------------
// out[i] = act( dis[i]*( sum_in xw[row]*dis[row] + xw[i]*dis[i] ) + b )
__global__ void k_aggregate(const float* __restrict__ in, float* __restrict__ out,
                            const float* __restrict__ bias, int n, int relu) {
    int node = blockIdx.x * 8 + (threadIdx.x >> 5);
    int lane = threadIdx.x & 31;
    if (node >= n) return;
    const float2* inp = (const float2*)in;
    float d = g_dis[node];
    float2 self = inp[(size_t)node * 32 + lane];
    float2 acc0 = make_float2(self.x * d, self.y * d);   // self-loop
    float2 acc1 = make_float2(0.f, 0.f);
    int s = g_off[node], e = g_off[node + 1];
    for (int base = s; base < e; base += 32) {
        int idx = base + lane;
        int2 pr = (idx < e) ? g_csr[idx] : make_int2(0, 0);
        int cnt = min(32, e - base);
        int j = 0;
        for (; j + 4 <= cnt; j += 4) {
            int   r0 = __shfl_sync(0xffffffffu, pr.x, j);
            float d0 = __int_as_float(__shfl_sync(0xffffffffu, pr.y, j));
            int   r1 = __shfl_sync(0xffffffffu, pr.x, j + 1);
            float d1 = __int_as_float(__shfl_sync(0xffffffffu, pr.y, j + 1));
            int   r2 = __shfl_sync(0xffffffffu, pr.x, j + 2);
            float d2 = __int_as_float(__shfl_sync(0xffffffffu, pr.y, j + 2));
            int   r3 = __shfl_sync(0xffffffffu, pr.x, j + 3);
            float d3 = __int_as_float(__shfl_sync(0xffffffffu, pr.y, j + 3));
            float2 v0 = inp[(size_t)r0 * 32 + lane];
            float2 v1 = inp[(size_t)r1 * 32 + lane];
            float2 v2 = inp[(size_t)r2 * 32 + lane];
            float2 v3 = inp[(size_t)r3 * 32 + lane];
            acc0.x = fmaf(v0.x, d0, acc0.x); acc0.y = fmaf(v0.y, d0, acc0.y);
            acc1.x = fmaf(v1.x, d1, acc1.x); acc1.y = fmaf(v1.y, d1, acc1.y);
            acc0.x = fmaf(v2.x, d2, acc0.x); acc0.y = fmaf(v2.y, d2, acc0.y);
            acc1.x = fmaf(v3.x, d3, acc1.x); acc1.y = fmaf(v3.y, d3, acc1.y);
        }
        for (; j < cnt; j++) {
            int   r  = __shfl_sync(0xffffffffu, pr.x, j);
            float dw = __int_as_float(__shfl_sync(0xffffffffu, pr.y, j));
            float2 v = inp[(size_t)r * 32 + lane];
            acc0.x = fmaf(v.x, dw, acc0.x);
            acc0.y = fmaf(v.y, dw, acc0.y);
        }
    }
    float ax = acc0.x + acc1.x, ay = acc0.y + acc1.y;
    float2 bv = ((const float2*)bias)[lane];
    float ox = fmaf(d, ax, bv.x);
    float oy = fmaf(d, ay, bv.y);
    if (relu) { ox = fmaxf(ox, 0.f); oy = fmaxf(oy, 0.f); }
    float2 o; o.x = ox; o.y = oy;
    ((float2*)out)[(size_t)node * 32 + lane] = o;
}

// ---------------- Decode: out[e] = dot(z[src], z[dst]) ----------------
__global__ void k_decode(const int* __restrict__ eli, const float* __restrict__ z,
                         float* __restrict__ out, int nL) {
    int w = blockIdx.x * 8 + (threadIdx.x >> 5);
    int lane = threadIdx.x & 31;
    if (w >= nL) return;
    int s = eli[w];
    int d = eli[nL + w];
    const float2* z2 = (const float2*)z;
    float2 a = z2[(size_t)s * 32 + lane];
    float2 b = z2[(size_t)d * 32 + lane];
    float p = a.x * b.x + a.y * b.y;
#pragma unroll
    for (int o = 16; o > 0; o >>= 1) p += __shfl_down_sync(0xffffffffu, p, o);
    if (lane == 0) out[w] = p;
}

// ---------------- launch ----------------
extern "C" void kernel_launch(void* const* d_in, const int* in_sizes, int n_in,
                              void* d_out, int out_size) {
    const float* x   = (const float*)d_in[0];
    const int*   ei  = (const int*)  d_in[1];
    const int*   eli = (const int*)  d_in[2];
    const float* W1  = (const float*)d_in[3];
    const float* b1  = (const float*)d_in[4];
    const float* W2  = (const float*)d_in[5];
    const float* b2  = (const float*)d_in[6];
    float* out = (float*)d_out;

    int n  = in_sizes[0] / 256;
    int nE = in_sizes[1] / 2;
    int nL = in_sizes[2] / 2;

    void *p_xw1, *p_h, *p_xw2, *p_z;
    cudaGetSymbolAddress(&p_xw1, g_xw1);
    cudaGetSymbolAddress(&p_h,   g_h);
    cudaGetSymbolAddress(&p_xw2, g_xw2);
    cudaGetSymbolAddress(&p_z,   g_z);

    // Fork: CSR build on side stream, GEMM1 concurrently on main stream.
    cudaEventRecord(g_evF, 0);
    cudaStreamWaitEvent(g_s2, g_evF, 0);

    k_count<<<(nE + 255) / 256, 256, 0, g_s2>>>(ei, nE);
    int nb = (n + 1023) / 1024;
    k_scan_fused<<<nb, 1024, 0, g_s2>>>(n, nb);
    k_scatter<<<(nE + 255) / 256, 256, 0, g_s2>>>(ei, nE);
    cudaEventRecord(g_evJ, g_s2);

    int gb = (n + 127) / 128;
    k_gemm_mma<256><<<gb, 256>>>(x, W1, (float*)p_xw1, n);   // concurrent with CSR

    // Join
    cudaStreamWaitEvent(0, g_evJ, 0);

    // layer 1 aggregate
    k_aggregate<<<(n + 7) / 8, 256>>>((const float*)p_xw1, (float*)p_h, b1, n, 1);
    // layer 2
    k_gemm_mma<64><<<gb, 256>>>((const float*)p_h, W2, (float*)p_xw2, n);
    k_aggregate<<<(n + 7) / 8, 256>>>((const float*)p_xw2, (float*)p_z, b2, n, 0);
    // decode
    k_decode<<<(nL + 7) / 8, 256>>>(eli, (const float*)p_z, out, nL);
}